// round 16
// baseline (speedup 1.0000x reference)
#include <cuda_runtime.h>
#include <math.h>
#include <stdint.h>
typedef unsigned long long ull;
typedef uint32_t u32;

#define NTHR 512
#define HB   32768
#define HALF_F 24640              // floats per half region
#define WT_F   8192               // weight offset within half (floats)
#define MBAR_B 98304              // mbar byte offset within half (24576*4)
#define SMEM_BYTES 197120

__device__ __align__(128) float g_X[(size_t)512 * 64 * 1024]; // x@W0[:512], [t*64+b][1024]
__device__ __align__(128) float g_T[8][HB];   // states [slot][dom(4)][col(512)][row(16)]; 7=h
__device__ __align__(128) float g_W2[(size_t)576 * 8192];     // [(jt*9+g)][k][ch(2)][j(8)]
__device__ unsigned int g_arr[4], g_gen[4];

__device__ __forceinline__ void fma2(ull &d, ull a, ull b) {
    asm("fma.rn.f32x2 %0, %1, %2, %0;" : "+l"(d) : "l"(a), "l"(b));
}
__device__ __forceinline__ ull dup2(float v) {
    ull r; asm("mov.b64 %0, {%1, %1};" : "=l"(r) : "f"(v)); return r;
}
__device__ __forceinline__ float2 unpk(ull v) {
    float2 f; asm("mov.b64 {%0, %1}, %2;" : "=f"(f.x), "=f"(f.y) : "l"(v)); return f;
}
__device__ __forceinline__ u32 smem_u32(const void* p) {
    u32 a; asm("{ .reg .u64 t; cvta.to.shared.u64 t, %1; cvt.u32.u64 %0, t; }" : "=r"(a) : "l"(p));
    return a;
}
__device__ __forceinline__ float ldcg(const float* p) {
    float v; asm("ld.global.cg.f32 %0, [%1];" : "=f"(v) : "l"(p)); return v;
}
__device__ __forceinline__ void half_bar(int h) {
    asm volatile("bar.sync %0, 256;" :: "r"(h + 1) : "memory");
}
__device__ __forceinline__ void grid_bar2(int dom, int h) {
    half_bar(h);
    if ((threadIdx.x & 255) == 0) {
        unsigned int gen = ((volatile unsigned int*)&g_gen[dom])[0];
        __threadfence();
        if (atomicAdd(&g_arr[dom], 1u) == 63u) {
            g_arr[dom] = 0u; __threadfence();
            ((volatile unsigned int*)&g_gen[dom])[0] = gen + 1u;
        } else {
            while (((volatile unsigned int*)&g_gen[dom])[0] == gen) { }
        }
        __threadfence();
    }
    half_bar(h);
}
__device__ __forceinline__ void mbar_wait(u32 mbar, u32 par) {
    asm volatile(
        "{\n\t.reg .pred P;\n"
        "W%=:\n\t"
        "mbarrier.try_wait.parity.acquire.cta.shared::cta.b64 P, [%0], %1;\n\t"
        "@!P bra W%=;\n\t}"
        :: "r"(mbar), "r"(par) : "memory");
}
__device__ __forceinline__ void bulk_cp(u32 dst, const void* src, u32 bytes, u32 mbar) {
    asm volatile(
        "cp.async.bulk.shared::cta.global.mbarrier::complete_tx::bytes [%0], [%1], %2, [%3];"
        :: "r"(dst), "l"(src), "r"(bytes), "r"(mbar) : "memory");
}
__device__ __forceinline__ float sigm_f(float x) {
    return __fdividef(1.f, 1.f + __expf(-x));
}
__device__ __forceinline__ float actf(int a, float x) {
    if (a == 0) {                                  // tanh, overflow-safe
        float ax = fabsf(x);
        float e = __expf(-2.f * ax);
        float r = __fdividef(1.f - e, 1.f + e);
        return copysignf(r, x);
    }
    if (a == 1) return fmaxf(x, 0.f);
    if (a == 2) return sigm_f(x);
    return x;
}

// ---------- prep: weight pack + hidden transpose + X precompute ----------
__global__ void __launch_bounds__(256) prep_kernel(const float* __restrict__ A,
    const float* __restrict__ hid, const float* __restrict__ W0, const float* __restrict__ Ws) {
    int bid = blockIdx.x, tid = threadIdx.x;
    if (bid < 576) {                       // pack: bid = jt*9+g -> [k][ch][8j]
        int jt = bid / 9, g = bid % 9;
        const float* src = (g == 8) ? (W0 + (size_t)512 * 1024) : (Ws + (size_t)g * 512 * 1024);
        float* dst = g_W2 + (size_t)bid * 8192;
#pragma unroll
        for (int it = 0; it < 8; ++it) {
            int d4 = (tid + it * 256) * 4;
            int k = d4 >> 4, ch = (d4 >> 3) & 1, jc = d4 & 7;
            *(float4*)(dst + d4) = *(const float4*)(src + (size_t)k * 1024 + ch * 512 + jt * 8 + jc);
        }
        return;
    }
    if (bid == 576) {                      // hT init: [dom][col][row16]
        for (int i = tid; i < HB; i += 256) {
            int b = i & 63, col = i >> 6;
            g_T[7][(size_t)(b >> 4) * 8192 + col * 16 + (b & 15)] = hid[(size_t)b * 512 + col];
        }
        return;
    }
    int idx = bid - 577;                   // X = inputs @ W0[:512]
    __shared__ ull   AsD[64][17];
    __shared__ float Bs[16][68];
    const int n0 = (idx & 15) * 64, m0 = (idx >> 4) * 64;
    const int tx = tid & 15, ty = tid >> 4;
    ull acc[4][2];
#pragma unroll
    for (int i = 0; i < 4; ++i) { acc[i][0] = 0; acc[i][1] = 0; }
    for (int k0 = 0; k0 < 512; k0 += 16) {
        {
            int am = tid >> 2, a4 = tid & 3;
            float4 v = *(const float4*)(A + (size_t)(m0 + am) * 512 + k0 + a4 * 4);
            AsD[am][a4*4+0]=dup2(v.x); AsD[am][a4*4+1]=dup2(v.y);
            AsD[am][a4*4+2]=dup2(v.z); AsD[am][a4*4+3]=dup2(v.w);
        }
        {
            int bk = tid >> 4, b4 = tid & 15;
            *(float4*)&Bs[bk][b4*4] = *(const float4*)(W0 + (size_t)(k0+bk)*1024 + n0 + b4*4);
        }
        __syncthreads();
#pragma unroll
        for (int k = 0; k < 16; ++k) {
            ulonglong2 b = *(const ulonglong2*)&Bs[k][tx*4];
#pragma unroll
            for (int i = 0; i < 4; ++i) { ull a = AsD[ty*4+i][k]; fma2(acc[i][0],a,b.x); fma2(acc[i][1],a,b.y); }
        }
        __syncthreads();
    }
#pragma unroll
    for (int i = 0; i < 4; ++i) {
        float2 lo = unpk(acc[i][0]), hi = unpk(acc[i][1]);
        *(float4*)(g_X + (size_t)(m0+ty*4+i)*1024 + n0 + tx*4) = make_float4(lo.x,lo.y,hi.x,hi.y);
    }
}

// ---------- one DAG level for one half (16 rows x 8 j, single TMA-bulk stage) ----------
// pred_dom points at this domain's contiguous 32KB slice [col(512)][row(16)].
template<int NG, bool BIAS, bool MEAN, bool S7>
__device__ __forceinline__ void phase(float* smh, u32 smhb, u32 mbar, u32 par,
    int dom, int jt, int t,
    int gi0, int gi1, int ac0, int ac1, int ds0, int ds1,
    const float* pred_dom, float* out, float& s7reg, int h)
{
    const int tid = threadIdx.x & 255;
    const int lane = tid & 31, kq = tid >> 5;
    const int rowl = lane & 15, jh = lane >> 4;
    const bool epi = (tid < 128);
    const int erow = tid & 15, ejc = (tid >> 4) & 7;
    const int ecol = jt * 8 + ejc;
    const int egrow = dom * 16 + erow;
    const size_t tidx = (size_t)dom * 8192 + ecol * 16 + erow;

    // ---- issue bulk staging (1 thread): states + NG weight tiles ----
    if (tid == 0) {
        const u32 bytes = (u32)(NG + 1) * 32768u;
        asm volatile("mbarrier.arrive.expect_tx.shared.b64 _, [%0], %1;"
                     :: "r"(mbar), "r"(bytes) : "memory");
        bulk_cp(smhb, pred_dom, 32768u, mbar);
#pragma unroll
        for (int g = 0; g < NG; ++g) {
            int gi = g ? gi1 : gi0;
            bulk_cp(smhb + (u32)((WT_F + g * 8192) * 4),
                    g_W2 + (size_t)(jt * 9 + gi) * 8192, 32768u, mbar);
        }
    }

    // ---- epilogue operand prefetch (hidden behind staging) ----
    float pre_sp = 0.f, pre_b0 = 0.f, pre_b1 = 0.f, pre_m = 0.f;
    if (epi) {
        pre_sp = ldcg(pred_dom + (size_t)ecol * 16 + erow);
        if (BIAS) {
            pre_b0 = ldcg(g_X + ((size_t)t * 64 + egrow) * 1024 + ecol);
            pre_b1 = ldcg(g_X + ((size_t)t * 64 + egrow) * 1024 + 512 + ecol);
        }
        if (MEAN) {
            float m = 0.f;
#pragma unroll
            for (int st = 1; st <= 6; ++st) m += ldcg(&g_T[st][tidx]);
            pre_m = m;
        }
    }

    mbar_wait(mbar, par);

    // ---- compute: warp kq handles k in [kq*64, kq*64+64) ----
    ull acc[NG][2][2];
#pragma unroll
    for (int g = 0; g < NG; ++g)
#pragma unroll
        for (int ch = 0; ch < 2; ++ch) { acc[g][ch][0] = 0; acc[g][ch][1] = 0; }
    const float* sbase = smh + kq * 64 * 16 + rowl;
    const float* wb    = smh + WT_F + kq * 64 * 16 + jh * 4;
#pragma unroll 8
    for (int kk = 0; kk < 64; ++kk) {
        ull sd = dup2(sbase[kk * 16]);
#pragma unroll
        for (int g = 0; g < NG; ++g) {
            const float* wg = wb + g * 8192 + kk * 16;
            ulonglong2 wc = *(const ulonglong2*)(wg);
            ulonglong2 wh = *(const ulonglong2*)(wg + 8);
            fma2(acc[g][0][0], sd, wc.x); fma2(acc[g][0][1], sd, wc.y);
            fma2(acc[g][1][0], sd, wh.x); fma2(acc[g][1][1], sd, wh.y);
        }
    }
    half_bar(h);

    // ---- reduction over 8 K-warps; red overlays the (dead) weight region ----
    ull* red = (ull*)(smh + WT_F);
#pragma unroll
    for (int g = 0; g < NG; ++g)
#pragma unroll
        for (int ch = 0; ch < 2; ++ch)
#pragma unroll
            for (int jp = 0; jp < 2; ++jp)
                red[(size_t)((((kq*2 + jh)*NG + g)*4) + ch*2 + jp)*16 + rowl] = acc[g][ch][jp];
    half_bar(h);

    if (epi) {
        const int ejh = ejc >> 2, ejp = (ejc >> 1) & 1, ehalf = ejc & 1;
        float mv = 0.f;
#pragma unroll
        for (int g = 0; g < NG; ++g) {
            float cs = 0.f, hs = 0.f;
#pragma unroll
            for (int q = 0; q < 8; ++q) {
                float2 a = unpk(red[(size_t)((((q*2 + ejh)*NG + g)*4) + 0 + ejp)*16 + erow]);
                float2 b = unpk(red[(size_t)((((q*2 + ejh)*NG + g)*4) + 2 + ejp)*16 + erow]);
                cs += ehalf ? a.y : a.x;
                hs += ehalf ? b.y : b.x;
            }
            if (BIAS) { cs += pre_b0; hs += pre_b1; }
            int act = g ? ac1 : ac0;
            float cg = sigm_f(cs);
            float hv = actf(act, hs);
            float nv = pre_sp + cg * (hv - pre_sp);
            if (S7) s7reg = nv;
            else if (!MEAN) g_T[g ? ds1 : ds0][tidx] = nv;
            if (MEAN) mv += nv;
        }
        if (MEAN) {
            float m = (pre_m + s7reg + mv) * 0.125f;
            out[(size_t)t * HB + (size_t)egrow * 512 + ecol] = m;
            g_T[7][tidx] = m;
        }
    }
    // order epilogue reads of `red` before the next phase's bulk staging writes
    half_bar(h);
}

__global__ void __launch_bounds__(NTHR, 1) recurrent_kernel(float* __restrict__ out, int tail)
{
    extern __shared__ float sm[];
    const int h = threadIdx.x >> 8;                 // half 0/1
    float* smh = sm + h * HALF_F;
    u32 smhb = smem_u32(smh);
    u32 mbar = smhb + MBAR_B;
    const int bid = blockIdx.x, jt = bid & 63, dp = bid >> 6;
    const int dom = dp * 2 + h;                     // this half's row domain (16 rows)
    float* T = &g_T[0][0];
    const size_t doff = (size_t)dom * 8192;
    float s7 = 0.f;
    u32 par = 0;

    if ((threadIdx.x & 255) == 0)
        asm volatile("mbarrier.init.shared.b64 [%0], 1;" :: "r"(mbar) : "memory");
    asm volatile("fence.proxy.async.shared::cta;" ::: "memory");
    __syncthreads();

    for (int t = 0; t < 512; ++t) {
        // P0: s0 = h + sig(c)*(tanh(hh)-h); gemm 8, bias X[t]
        phase<1, true , false, false>(smh, smhb, mbar, par, dom, jt, t, 8, 0, 0, 0, 0, 0,
                                      T + 7*HB + doff, out, s7, h); par ^= 1;
        grid_bar2(dom, h);
        // P1: s1(tanh), s2(relu) from s0
        phase<2, false, false, false>(smh, smhb, mbar, par, dom, jt, t, 0, 1, 0, 1, 1, 2,
                                      T + 0*HB + doff, out, s7, h); par ^= 1;
        grid_bar2(dom, h);
        // P2a: s3(sig), s4(id) from s1 ; P2b: s5(tanh), s6(relu) from s2
        phase<2, false, false, false>(smh, smhb, mbar, par, dom, jt, t, 2, 3, 2, 3, 3, 4,
                                      T + 1*HB + doff, out, s7, h); par ^= 1;
        phase<2, false, false, false>(smh, smhb, mbar, par, dom, jt, t, 4, 5, 0, 1, 5, 6,
                                      T + 2*HB + doff, out, s7, h); par ^= 1;
        grid_bar2(dom, h);
        // P3a: s7(sig) from s3 (kept in reg) ; P3b: s8(id) from s4 + mean -> out[t]
        phase<1, false, false, true >(smh, smhb, mbar, par, dom, jt, t, 6, 0, 2, 0, 0, 0,
                                      T + 3*HB + doff, out, s7, h); par ^= 1;
        phase<1, false, true , false>(smh, smhb, mbar, par, dom, jt, t, 7, 0, 3, 0, 0, 0,
                                      T + 4*HB + doff, out, s7, h); par ^= 1;
        grid_bar2(dom, h);
    }
    // tail: domain-local copy of final hidden (rows dom*16..+16)
    if (tail && jt < 16) {
        int row = dom * 16 + jt;
        const float* src = out + (size_t)511 * HB + (size_t)row * 512;
        float* dst = out + (size_t)512 * HB + (size_t)row * 512;
        int tl = threadIdx.x & 255;
        dst[tl]       = src[tl];
        dst[tl + 256] = src[tl + 256];
    }
}

extern "C" void kernel_launch(void* const* d_in, const int* in_sizes, int n_in,
                              void* d_out, int out_size) {
    const float* inputs = (const float*)d_in[0];
    const float* hidden = (const float*)d_in[1];
    const float* W0     = (const float*)d_in[2];
    const float* Ws     = (const float*)d_in[3];
    float* out = (float*)d_out;

    prep_kernel<<<577 + 8192, 256>>>(inputs, hidden, W0, Ws);

    cudaFuncSetAttribute(recurrent_kernel,
                         cudaFuncAttributeMaxDynamicSharedMemorySize, SMEM_BYTES);
    int tail = (out_size >= 513 * HB) ? 1 : 0;
    recurrent_kernel<<<128, NTHR, SMEM_BYTES>>>(out, tail);
}

// round 17
// speedup vs baseline: 1.0735x; 1.0735x over previous
#include <cuda_runtime.h>
#include <math.h>
#include <stdint.h>
typedef unsigned long long ull;
typedef uint32_t u32;

#define NTHR 512
#define HB   32768
#define HALF_F 28672              // floats per half region (112KB)
#define WT_F   8192               // weight offset within half (floats)
#define RED_F  24576              // reduction offset within half (floats)
#define MBAR_OFF 229376           // byte offset of mbar block (after both halves)
#define SMEM_BYTES 229504

__device__ __align__(128) float g_X[(size_t)512 * 64 * 1024]; // x@W0[:512], [t*64+b][1024]
__device__ __align__(128) float g_T[8][HB];   // states [slot][dom(4)][col(512)][row(16)]; 7=h
__device__ __align__(128) float g_W2[(size_t)576 * 8192];     // [(jt*9+g)][k][ch(2)][j(8)]
__device__ unsigned int g_arr[4], g_gen[4];

__device__ __forceinline__ void fma2(ull &d, ull a, ull b) {
    asm("fma.rn.f32x2 %0, %1, %2, %0;" : "+l"(d) : "l"(a), "l"(b));
}
__device__ __forceinline__ ull dup2(float v) {
    ull r; asm("mov.b64 %0, {%1, %1};" : "=l"(r) : "f"(v)); return r;
}
__device__ __forceinline__ float2 unpk(ull v) {
    float2 f; asm("mov.b64 {%0, %1}, %2;" : "=f"(f.x), "=f"(f.y) : "l"(v)); return f;
}
__device__ __forceinline__ u32 smem_u32(const void* p) {
    u32 a; asm("{ .reg .u64 t; cvta.to.shared.u64 t, %1; cvt.u32.u64 %0, t; }" : "=r"(a) : "l"(p));
    return a;
}
__device__ __forceinline__ float ldcg(const float* p) {
    float v; asm("ld.global.cg.f32 %0, [%1];" : "=f"(v) : "l"(p)); return v;
}
__device__ __forceinline__ void half_bar(int h) {
    asm volatile("bar.sync %0, 256;" :: "r"(h + 1) : "memory");
}
__device__ __forceinline__ void grid_bar2(int dom, int h) {
    half_bar(h);
    if ((threadIdx.x & 255) == 0) {
        unsigned int gen = ((volatile unsigned int*)&g_gen[dom])[0];
        __threadfence();
        if (atomicAdd(&g_arr[dom], 1u) == 63u) {
            g_arr[dom] = 0u; __threadfence();
            ((volatile unsigned int*)&g_gen[dom])[0] = gen + 1u;
        } else {
            while (((volatile unsigned int*)&g_gen[dom])[0] == gen) { }
        }
        __threadfence();
    }
    half_bar(h);
}
__device__ __forceinline__ void mbar_expect(u32 mbar, u32 bytes) {
    asm volatile("mbarrier.arrive.expect_tx.shared.b64 _, [%0], %1;"
                 :: "r"(mbar), "r"(bytes) : "memory");
}
__device__ __forceinline__ void mbar_wait(u32 mbar, u32 par) {
    asm volatile(
        "{\n\t.reg .pred P;\n"
        "W%=:\n\t"
        "mbarrier.try_wait.parity.acquire.cta.shared::cta.b64 P, [%0], %1;\n\t"
        "@!P bra W%=;\n\t}"
        :: "r"(mbar), "r"(par) : "memory");
}
__device__ __forceinline__ void bulk_cp(u32 dst, const void* src, u32 bytes, u32 mbar) {
    asm volatile(
        "cp.async.bulk.shared::cta.global.mbarrier::complete_tx::bytes [%0], [%1], %2, [%3];"
        :: "r"(dst), "l"(src), "r"(bytes), "r"(mbar) : "memory");
}
__device__ __forceinline__ float sigm_f(float x) {
    return __fdividef(1.f, 1.f + __expf(-x));
}
__device__ __forceinline__ float actf(int a, float x) {
    if (a == 0) {                                  // tanh, overflow-safe
        float ax = fabsf(x);
        float e = __expf(-2.f * ax);
        float r = __fdividef(1.f - e, 1.f + e);
        return copysignf(r, x);
    }
    if (a == 1) return fmaxf(x, 0.f);
    if (a == 2) return sigm_f(x);
    return x;
}

// ---------- prep: weight pack + hidden transpose + X precompute ----------
__global__ void __launch_bounds__(256) prep_kernel(const float* __restrict__ A,
    const float* __restrict__ hid, const float* __restrict__ W0, const float* __restrict__ Ws) {
    int bid = blockIdx.x, tid = threadIdx.x;
    if (bid < 576) {                       // pack: bid = jt*9+g -> [k][ch][8j]
        int jt = bid / 9, g = bid % 9;
        const float* src = (g == 8) ? (W0 + (size_t)512 * 1024) : (Ws + (size_t)g * 512 * 1024);
        float* dst = g_W2 + (size_t)bid * 8192;
#pragma unroll
        for (int it = 0; it < 8; ++it) {
            int d4 = (tid + it * 256) * 4;
            int k = d4 >> 4, ch = (d4 >> 3) & 1, jc = d4 & 7;
            *(float4*)(dst + d4) = *(const float4*)(src + (size_t)k * 1024 + ch * 512 + jt * 8 + jc);
        }
        return;
    }
    if (bid == 576) {                      // hT init: [dom][col][row16]
        for (int i = tid; i < HB; i += 256) {
            int b = i & 63, col = i >> 6;
            g_T[7][(size_t)(b >> 4) * 8192 + col * 16 + (b & 15)] = hid[(size_t)b * 512 + col];
        }
        return;
    }
    int idx = bid - 577;                   // X = inputs @ W0[:512]
    __shared__ ull   AsD[64][17];
    __shared__ float Bs[16][68];
    const int n0 = (idx & 15) * 64, m0 = (idx >> 4) * 64;
    const int tx = tid & 15, ty = tid >> 4;
    ull acc[4][2];
#pragma unroll
    for (int i = 0; i < 4; ++i) { acc[i][0] = 0; acc[i][1] = 0; }
    for (int k0 = 0; k0 < 512; k0 += 16) {
        {
            int am = tid >> 2, a4 = tid & 3;
            float4 v = *(const float4*)(A + (size_t)(m0 + am) * 512 + k0 + a4 * 4);
            AsD[am][a4*4+0]=dup2(v.x); AsD[am][a4*4+1]=dup2(v.y);
            AsD[am][a4*4+2]=dup2(v.z); AsD[am][a4*4+3]=dup2(v.w);
        }
        {
            int bk = tid >> 4, b4 = tid & 15;
            *(float4*)&Bs[bk][b4*4] = *(const float4*)(W0 + (size_t)(k0+bk)*1024 + n0 + b4*4);
        }
        __syncthreads();
#pragma unroll
        for (int k = 0; k < 16; ++k) {
            ulonglong2 b = *(const ulonglong2*)&Bs[k][tx*4];
#pragma unroll
            for (int i = 0; i < 4; ++i) { ull a = AsD[ty*4+i][k]; fma2(acc[i][0],a,b.x); fma2(acc[i][1],a,b.y); }
        }
        __syncthreads();
    }
#pragma unroll
    for (int i = 0; i < 4; ++i) {
        float2 lo = unpk(acc[i][0]), hi = unpk(acc[i][1]);
        *(float4*)(g_X + (size_t)(m0+ty*4+i)*1024 + n0 + tx*4) = make_float4(lo.x,lo.y,hi.x,hi.y);
    }
}

// ---------- one DAG level for one half ----------
// SPRE: this phase's state + weights were already prefetched (wait mbar_w only).
// Post-compute: prefetch next phase's nNG weight tiles (+ optional next state) on mbar_w.
template<int NG, bool BIAS, bool MEAN, bool S7, bool SPRE>
__device__ __forceinline__ void phase(float* smh, u32 smhb, u32 mbw, u32 mbs,
    u32 pw, u32 ps, int dom, int jt, int t,
    int gi0, int gi1, int ac0, int ac1, int ds0, int ds1,
    const float* pred_dom,
    int ngi0, int ngi1, int nNG, const float* nstate,
    float* out, float& s7reg, int h)
{
    const int tid = threadIdx.x & 255;
    const int lane = tid & 31, kq = tid >> 5;
    const int rowl = lane & 15, jh = lane >> 4;

    // epilogue mapping (widened to 256 threads when NG==2)
    int eg, eidx; bool act;
    if (NG == 2) { eg = tid >> 7; eidx = tid & 127; act = true; }
    else         { eg = 0;        eidx = tid;       act = (tid < 128); }
    const int erow = eidx & 15, ejc = (eidx >> 4) & 7;
    const int ecol = jt * 8 + ejc;
    const int egrow = dom * 16 + erow;
    const size_t tidx = (size_t)dom * 8192 + ecol * 16 + erow;

    // ---- issue state staging if not prefetched ----
    if (!SPRE && tid == 0) {
        mbar_expect(mbs, 32768u);
        bulk_cp(smhb, pred_dom, 32768u, mbs);
    }

    // ---- epilogue operand prefetch (hidden behind staging) ----
    float pre_sp = 0.f, pre_b0 = 0.f, pre_b1 = 0.f, pre_m = 0.f;
    if (act) {
        pre_sp = ldcg(pred_dom + (size_t)ecol * 16 + erow);
        if (BIAS) {
            pre_b0 = ldcg(g_X + ((size_t)t * 64 + egrow) * 1024 + ecol);
            pre_b1 = ldcg(g_X + ((size_t)t * 64 + egrow) * 1024 + 512 + ecol);
        }
        if (MEAN) {
            float m = 0.f;
#pragma unroll
            for (int st = 1; st <= 6; ++st) m += ldcg(&g_T[st][tidx]);
            pre_m = m;
        }
    }

    mbar_wait(mbw, pw);
    if (!SPRE) mbar_wait(mbs, ps);

    // ---- compute: warp kq handles k in [kq*64, kq*64+64) ----
    ull acc[NG][2][2];
#pragma unroll
    for (int g = 0; g < NG; ++g)
#pragma unroll
        for (int ch = 0; ch < 2; ++ch) { acc[g][ch][0] = 0; acc[g][ch][1] = 0; }
    const float* sbase = smh + kq * 64 * 16 + rowl;
    const float* wb    = smh + WT_F + kq * 64 * 16 + jh * 4;
#pragma unroll 8
    for (int kk = 0; kk < 64; ++kk) {
        ull sd = dup2(sbase[kk * 16]);
#pragma unroll
        for (int g = 0; g < NG; ++g) {
            const float* wg = wb + g * 8192 + kk * 16;
            ulonglong2 wc = *(const ulonglong2*)(wg);
            ulonglong2 wh = *(const ulonglong2*)(wg + 8);
            fma2(acc[g][0][0], sd, wc.x); fma2(acc[g][0][1], sd, wc.y);
            fma2(acc[g][1][0], sd, wh.x); fma2(acc[g][1][1], sd, wh.y);
        }
    }
    half_bar(h);   // weights + state regions now dead

    // ---- prefetch next phase's weights (+ optional ready state) on mbar_w ----
    if (tid == 0 && nNG > 0) {
        u32 bytes = (u32)nNG * 32768u + (nstate ? 32768u : 0u);
        mbar_expect(mbw, bytes);
        bulk_cp(smhb + (u32)(WT_F * 4), g_W2 + (size_t)(jt * 9 + ngi0) * 8192, 32768u, mbw);
        if (nNG > 1)
            bulk_cp(smhb + (u32)((WT_F + 8192) * 4), g_W2 + (size_t)(jt * 9 + ngi1) * 8192,
                    32768u, mbw);
        if (nstate) bulk_cp(smhb, nstate, 32768u, mbw);
    }

    // ---- reduction over 8 K-warps into dedicated red region ----
    ull* red = (ull*)(smh + RED_F);
#pragma unroll
    for (int g = 0; g < NG; ++g)
#pragma unroll
        for (int ch = 0; ch < 2; ++ch)
#pragma unroll
            for (int jp = 0; jp < 2; ++jp)
                red[(size_t)((((kq*2 + jh)*NG + g)*4) + ch*2 + jp)*16 + rowl] = acc[g][ch][jp];
    half_bar(h);

    if (act) {
        const int ejh = ejc >> 2, ejp = (ejc >> 1) & 1, ehalf = ejc & 1;
        float cs = 0.f, hs = 0.f;
#pragma unroll
        for (int q = 0; q < 8; ++q) {
            float2 a = unpk(red[(size_t)((((q*2 + ejh)*NG + eg)*4) + 0 + ejp)*16 + erow]);
            float2 b = unpk(red[(size_t)((((q*2 + ejh)*NG + eg)*4) + 2 + ejp)*16 + erow]);
            cs += ehalf ? a.y : a.x;
            hs += ehalf ? b.y : b.x;
        }
        if (BIAS) { cs += pre_b0; hs += pre_b1; }
        int actid = eg ? ac1 : ac0;
        float cg = sigm_f(cs);
        float hv = actf(actid, hs);
        float nv = pre_sp + cg * (hv - pre_sp);
        if (S7) s7reg = nv;
        else if (!MEAN) g_T[eg ? ds1 : ds0][tidx] = nv;
        if (MEAN) {
            float m = (pre_m + s7reg + nv) * 0.125f;
            out[(size_t)t * HB + (size_t)egrow * 512 + ecol] = m;
            g_T[7][tidx] = m;
        }
    }
    // NOTE: no trailing bar needed — next phase's red writes are ordered after
    // its own post-compute half_bar, which epilogue threads also pass through.
}

__global__ void __launch_bounds__(NTHR, 1) recurrent_kernel(float* __restrict__ out, int tail)
{
    extern __shared__ float sm[];
    const int h = threadIdx.x >> 8;                 // half 0/1
    float* smh = sm + h * HALF_F;
    u32 smhb = smem_u32(smh);
    u32 mbbase = smem_u32(sm) + MBAR_OFF;
    u32 mbw = mbbase + h * 16, mbs = mbbase + h * 16 + 8;
    const int bid = blockIdx.x, jt = bid & 63, dp = bid >> 6;
    const int dom = dp * 2 + h;                     // this half's row domain (16 rows)
    float* T = &g_T[0][0];
    const size_t doff = (size_t)dom * 8192;
    float s7 = 0.f;
    u32 pw = 0, ps = 0;

    if ((threadIdx.x & 255) == 0) {
        asm volatile("mbarrier.init.shared.b64 [%0], 1;" :: "r"(mbw) : "memory");
        asm volatile("mbarrier.init.shared.b64 [%0], 1;" :: "r"(mbs) : "memory");
    }
    asm volatile("fence.proxy.async.shared::cta;" ::: "memory");
    __syncthreads();

    // prologue: prefetch t=0 P0 weights (gi=8)
    if ((threadIdx.x & 255) == 0) {
        mbar_expect(mbw, 32768u);
        bulk_cp(smhb + (u32)(WT_F * 4), g_W2 + (size_t)(jt * 9 + 8) * 8192, 32768u, mbw);
    }

    for (int t = 0; t < 512; ++t) {
        // P0: s0 = h + sig(c)*(tanh(hh)-h); gemm 8, bias X[t]; prefetch W(0,1)
        phase<1, true , false, false, false>(smh, smhb, mbw, mbs, pw, ps, dom, jt, t,
            8, 0, 0, 0, 0, 0, T + 7*HB + doff, 0, 1, 2, nullptr, out, s7, h);
        pw ^= 1; ps ^= 1;
        grid_bar2(dom, h);
        // P1: s1(tanh), s2(relu) from s0; prefetch W(2,3)
        phase<2, false, false, false, false>(smh, smhb, mbw, mbs, pw, ps, dom, jt, t,
            0, 1, 0, 1, 1, 2, T + 0*HB + doff, 2, 3, 2, nullptr, out, s7, h);
        pw ^= 1; ps ^= 1;
        grid_bar2(dom, h);
        // P2a: s3(sig), s4(id) from s1; prefetch W(4,5) + state s2
        phase<2, false, false, false, false>(smh, smhb, mbw, mbs, pw, ps, dom, jt, t,
            2, 3, 2, 3, 3, 4, T + 1*HB + doff, 4, 5, 2, T + 2*HB + doff, out, s7, h);
        pw ^= 1; ps ^= 1;
        // P2b: s5(tanh), s6(relu) from s2 (fully prefetched); prefetch W(6)
        phase<2, false, false, false, true >(smh, smhb, mbw, mbs, pw, ps, dom, jt, t,
            4, 5, 0, 1, 5, 6, T + 2*HB + doff, 6, 0, 1, nullptr, out, s7, h);
        pw ^= 1;
        grid_bar2(dom, h);
        // P3a: s7(sig) from s3 (kept in reg); prefetch W(7) + state s4
        phase<1, false, false, true , false>(smh, smhb, mbw, mbs, pw, ps, dom, jt, t,
            6, 0, 2, 0, 0, 0, T + 3*HB + doff, 7, 0, 1, T + 4*HB + doff, out, s7, h);
        pw ^= 1; ps ^= 1;
        // P3b: s8(id) from s4 (fully prefetched) + mean -> out[t]; prefetch next-t W(8)
        phase<1, false, true , false, true >(smh, smhb, mbw, mbs, pw, ps, dom, jt, t,
            7, 0, 3, 0, 0, 0, T + 4*HB + doff, 8, 0, (t < 511 ? 1 : 0), nullptr, out, s7, h);
        pw ^= 1;
        grid_bar2(dom, h);
    }
    // tail: domain-local copy of final hidden (rows dom*16..+16)
    if (tail && jt < 16) {
        int row = dom * 16 + jt;
        const float* src = out + (size_t)511 * HB + (size_t)row * 512;
        float* dst = out + (size_t)512 * HB + (size_t)row * 512;
        int tl = threadIdx.x & 255;
        dst[tl]       = src[tl];
        dst[tl + 256] = src[tl + 256];
    }
}

extern "C" void kernel_launch(void* const* d_in, const int* in_sizes, int n_in,
                              void* d_out, int out_size) {
    const float* inputs = (const float*)d_in[0];
    const float* hidden = (const float*)d_in[1];
    const float* W0     = (const float*)d_in[2];
    const float* Ws     = (const float*)d_in[3];
    float* out = (float*)d_out;

    prep_kernel<<<577 + 8192, 256>>>(inputs, hidden, W0, Ws);

    cudaFuncSetAttribute(recurrent_kernel,
                         cudaFuncAttributeMaxDynamicSharedMemorySize, SMEM_BYTES);
    int tail = (out_size >= 513 * HB) ? 1 : 0;
    recurrent_kernel<<<128, NTHR, SMEM_BYTES>>>(out, tail);
}